// round 13
// baseline (speedup 1.0000x reference)
#include <cuda_runtime.h>
#include <math.h>

#define NN 100000
#define NB 5000
#define NE 3200000
#define SCAN_CHUNK 1024
#define SCAN_NBLK ((NN + SCAN_CHUNK - 1) / SCAN_CHUNK)   // 98
#define DBINS 256

// ---- device scratch ----
__device__ __align__(16) float g_h[NN * 16];    // padded h rows (slot 15 = 0)
__device__ __align__(16) float g_agg[NN * 16];  // padded agg
__device__ float g_b[NN * 19];
__device__ __align__(8) int2 g_adj[NE];         // CSC: {src row, norm bits}, sorted by col
__device__ int   g_cnt[NN];
__device__ int   g_off[NN];
__device__ int   g_cursor[NN];
__device__ int   g_bsum[SCAN_NBLK];
__device__ int   g_dhist[DBINS];                // degree histogram bins
__device__ int   g_perm[NN];                    // degree-sorted node order
__device__ float g_dinv[NN];
__device__ float g_d2[NN];       // 1/deg (deg = cnt+1)
__device__ float g_sum;
__device__ int   g_is64;

// ---- detect edge dtype + init counters ----
__global__ void k_init(const int* __restrict__ ewords) {
    int v = blockIdx.x * blockDim.x + threadIdx.x;
    if (v < NN) { g_cnt[v] = 0; g_cursor[v] = 0; }
    if (v < DBINS) g_dhist[v] = 0;
    if (v == 0) {
        int nonzero = 0;
        for (int i = 0; i < 64; i++) nonzero |= ewords[2 * i + 1];
        g_is64 = (nonzero == 0) ? 1 : 0;
        g_sum = 0.0f;
    }
}

// ---- in-degree histogram over col (2 edges/thread, vector loads) ----
__global__ void k_deg(const void* __restrict__ edges) {
    int i = blockIdx.x * blockDim.x + threadIdx.x;
    if (i >= NE / 2) return;
    int c0, c1;
    if (g_is64) {
        longlong2 cc = ((const longlong2*)edges)[NE / 2 + i];
        c0 = (int)cc.x; c1 = (int)cc.y;
    } else {
        int2 cc = ((const int2*)edges)[NE / 2 + i];
        c0 = cc.x; c1 = cc.y;
    }
    if ((unsigned)c0 < (unsigned)NN) atomicAdd(&g_cnt[c0], 1);
    if ((unsigned)c1 < (unsigned)NN) atomicAdd(&g_cnt[c1], 1);
}

// ---- blocked exclusive scan of cnt -> off ----
__global__ void k_scan1() {
    __shared__ int s[SCAN_CHUNK];
    int i = blockIdx.x * SCAN_CHUNK + threadIdx.x;
    int v = (i < NN) ? g_cnt[i] : 0;
    s[threadIdx.x] = v;
    __syncthreads();
    for (int d = 1; d < SCAN_CHUNK; d <<= 1) {
        int t = (threadIdx.x >= d) ? s[threadIdx.x - d] : 0;
        __syncthreads();
        s[threadIdx.x] += t;
        __syncthreads();
    }
    if (i < NN) g_off[i] = s[threadIdx.x] - v;
    if (threadIdx.x == SCAN_CHUNK - 1) g_bsum[blockIdx.x] = s[SCAN_CHUNK - 1];
}

__global__ void k_scan2() {
    __shared__ int s[128];
    int tid = threadIdx.x;
    int v = (tid < SCAN_NBLK) ? g_bsum[tid] : 0;
    s[tid] = v;
    __syncthreads();
    for (int d = 1; d < 128; d <<= 1) {
        int t = (tid >= d) ? s[tid - d] : 0;
        __syncthreads();
        s[tid] += t;
        __syncthreads();
    }
    if (tid < SCAN_NBLK) g_bsum[tid] = s[tid] - v;
}

// ---- scan fixup + dinv/d2 + degree histogram ----
__global__ void k_scan3() {
    int i = blockIdx.x * blockDim.x + threadIdx.x;
    if (i >= NN) return;
    g_off[i] += g_bsum[i / SCAN_CHUNK];
    int c = g_cnt[i];
    float d = (float)(c + 1);
    g_dinv[i] = 1.0f / sqrtf(d);
    g_d2[i]   = 1.0f / d;
    atomicAdd(&g_dhist[c < DBINS ? c : DBINS - 1], 1);
}

// ---- exclusive scan of the 256 degree bins (1 block) ----
__global__ void k_dscan() {
    __shared__ int s[DBINS];
    int tid = threadIdx.x;
    int v = g_dhist[tid];
    s[tid] = v;
    __syncthreads();
    for (int d = 1; d < DBINS; d <<= 1) {
        int t = (tid >= d) ? s[tid - d] : 0;
        __syncthreads();
        s[tid] += t;
        __syncthreads();
    }
    g_dhist[tid] = s[tid] - v;   // becomes cursor base
}

// ---- place nodes into degree-sorted order ----
__global__ void k_dplace() {
    int v = blockIdx.x * blockDim.x + threadIdx.x;
    if (v >= NN) return;
    int c = g_cnt[v];
    int b = c < DBINS ? c : DBINS - 1;
    int p = atomicAdd(&g_dhist[b], 1);
    g_perm[p] = v;
}

// ---- place edges into CSC (2 edges/thread, vector loads) ----
__global__ void k_place(const void* __restrict__ edges) {
    int i = blockIdx.x * blockDim.x + threadIdx.x;
    if (i >= NE / 2) return;
    int r0, r1, c0, c1;
    if (g_is64) {
        longlong2 rr = ((const longlong2*)edges)[i];
        longlong2 cc = ((const longlong2*)edges)[NE / 2 + i];
        r0 = (int)rr.x; r1 = (int)rr.y;
        c0 = (int)cc.x; c1 = (int)cc.y;
    } else {
        int2 rr = ((const int2*)edges)[i];
        int2 cc = ((const int2*)edges)[NE / 2 + i];
        r0 = rr.x; r1 = rr.y;
        c0 = cc.x; c1 = cc.y;
    }
    if ((unsigned)r0 >= (unsigned)NN) r0 = 0;
    if ((unsigned)r1 >= (unsigned)NN) r1 = 0;
    if ((unsigned)c0 >= (unsigned)NN) c0 = 0;
    if ((unsigned)c1 >= (unsigned)NN) c1 = 0;
    int p0 = atomicAdd(&g_cursor[c0], 1);
    int2 rec0; rec0.x = r0; rec0.y = __float_as_int(g_dinv[r0] * g_dinv[c0]);
    g_adj[g_off[c0] + p0] = rec0;
    int p1 = atomicAdd(&g_cursor[c1], 1);
    int2 rec1; rec1.x = r1; rec1.y = __float_as_int(g_dinv[r1] * g_dinv[c1]);
    g_adj[g_off[c1] + p1] = rec1;
}

// ---- b = [x1|x2t] W4^T + b4 ; agg0 = x1 W1^T + b1 - bg ----
__global__ void k_ab(const float* __restrict__ x1, const float* __restrict__ x2,
                     const float* __restrict__ W4, const float* __restrict__ b4,
                     const float* __restrict__ W1, const float* __restrict__ b1,
                     const float* __restrict__ bg) {
    __shared__ float sW4[19 * 19], sb4[19], sW1[15 * 15], sb1[15], sbg[15];
    for (int i = threadIdx.x; i < 19 * 19; i += blockDim.x) sW4[i] = W4[i];
    for (int i = threadIdx.x; i < 15 * 15; i += blockDim.x) sW1[i] = W1[i];
    if (threadIdx.x < 19) sb4[threadIdx.x] = b4[threadIdx.x];
    if (threadIdx.x < 15) { sb1[threadIdx.x] = b1[threadIdx.x]; sbg[threadIdx.x] = bg[threadIdx.x]; }
    __syncthreads();

    int v = blockIdx.x * blockDim.x + threadIdx.x;
    if (v >= NN) return;

    float in[19];
    const float* x1r = x1 + (size_t)v * 15;
#pragma unroll
    for (int k = 0; k < 15; k++) in[k] = x1r[k];
    const float* x2r = x2 + (size_t)(v % NB) * 4;
#pragma unroll
    for (int k = 0; k < 4; k++) in[15 + k] = x2r[k];

    float* brow = g_b + (size_t)v * 19;
#pragma unroll
    for (int j = 0; j < 19; j++) {
        float acc = sb4[j];
#pragma unroll
        for (int k = 0; k < 19; k++) acc = fmaf(sW4[j * 19 + k], in[k], acc);
        brow[j] = acc;
    }

    float* arow = g_agg + (size_t)v * 16;
#pragma unroll
    for (int i = 0; i < 15; i++) {
        float acc = sb1[i] - sbg[i];
#pragma unroll
        for (int k = 0; k < 15; k++) acc = fmaf(sW1[i * 15 + k], in[k], acc);
        arow[i] = acc;
    }
    arow[15] = 0.0f;
}

// ---- kernel H: a = relu(agg+bg); h = Wg [a;b] ----
__global__ void k_H(const float* __restrict__ Wg, const float* __restrict__ bg) {
    __shared__ float sWg[15 * 34], sbg[15];
    for (int i = threadIdx.x; i < 15 * 34; i += blockDim.x) sWg[i] = Wg[i];
    if (threadIdx.x < 15) sbg[threadIdx.x] = bg[threadIdx.x];
    __syncthreads();

    int v = blockIdx.x * blockDim.x + threadIdx.x;
    if (v >= NN) return;

    float a[15], bb[19];
    const float* arow = g_agg + (size_t)v * 16;
#pragma unroll
    for (int i = 0; i < 15; i++) a[i] = fmaxf(arow[i] + sbg[i], 0.0f);
    const float* brow = g_b + (size_t)v * 19;
#pragma unroll
    for (int j = 0; j < 19; j++) bb[j] = brow[j];

    float* hrow = g_h + (size_t)v * 16;
#pragma unroll
    for (int o = 0; o < 15; o++) {
        float acc = 0.0f;
        const float* w = sWg + o * 34;
#pragma unroll
        for (int k = 0; k < 15; k++) acc = fmaf(w[k], a[k], acc);
#pragma unroll
        for (int k = 0; k < 19; k++) acc = fmaf(w[15 + k], bb[k], acc);
        hrow[o] = acc;
    }
    hrow[15] = 0.0f;
}

__device__ __forceinline__ float4 fma4(float4 p, float w, float4 a) {
    a.x = fmaf(p.x, w, a.x);
    a.y = fmaf(p.y, w, a.y);
    a.z = fmaf(p.z, w, a.z);
    a.w = fmaf(p.w, w, a.w);
    return a;
}

// ---- gather: 4 threads/node, degree-sorted order, float4 LDG.128 ----
__global__ void k_gather() {
    int idx = blockIdx.x * 64 + (threadIdx.x >> 2);   // 256 threads = 64 nodes/block
    int t = threadIdx.x & 3;                          // float4 quarter of the row
    if (idx >= NN) return;
    int v = g_perm[idx];                              // degree-sorted node

    int off = g_off[v];
    int cnt = g_cnt[v];
    const int2* __restrict__ ap = g_adj + off;
    const float4* __restrict__ h4 = reinterpret_cast<const float4*>(g_h);

    float d2 = g_d2[v];
    float4 acc = h4[(size_t)v * 4 + t];               // self loop
    acc.x *= d2; acc.y *= d2; acc.z *= d2; acc.w *= d2;
    float4 ac1 = make_float4(0.f, 0.f, 0.f, 0.f);

    int j = 0;
    for (; j + 4 <= cnt; j += 4) {
        int2 e0 = __ldg(ap + j + 0);
        int2 e1 = __ldg(ap + j + 1);
        int2 e2 = __ldg(ap + j + 2);
        int2 e3 = __ldg(ap + j + 3);
        float4 p0 = h4[(size_t)e0.x * 4 + t];
        float4 p1 = h4[(size_t)e1.x * 4 + t];
        float4 p2 = h4[(size_t)e2.x * 4 + t];
        float4 p3 = h4[(size_t)e3.x * 4 + t];
        acc = fma4(p0, __int_as_float(e0.y), acc);
        ac1 = fma4(p1, __int_as_float(e1.y), ac1);
        acc = fma4(p2, __int_as_float(e2.y), acc);
        ac1 = fma4(p3, __int_as_float(e3.y), ac1);
    }
    for (; j < cnt; j++) {
        int2 e = __ldg(ap + j);
        acc = fma4(h4[(size_t)e.x * 4 + t], __int_as_float(e.y), acc);
    }
    acc.x += ac1.x; acc.y += ac1.y; acc.z += ac1.z; acc.w += ac1.w;
    reinterpret_cast<float4*>(g_agg)[(size_t)v * 4 + t] = acc;   // coalesced STG.128
}

// ---- final: a = relu(agg+bg); sum_v W3 . [a;b] ----
__global__ void k_final(const float* __restrict__ W3, const float* __restrict__ bg) {
    __shared__ float sW3[34], sbg[15];
    __shared__ float warpsum[32];
    if (threadIdx.x < 34) sW3[threadIdx.x] = W3[threadIdx.x];
    if (threadIdx.x < 15) sbg[threadIdx.x] = bg[threadIdx.x];
    __syncthreads();

    int v = blockIdx.x * blockDim.x + threadIdx.x;
    float acc = 0.0f;
    if (v < NN) {
        const float* arow = g_agg + (size_t)v * 16;
#pragma unroll
        for (int i = 0; i < 15; i++) {
            float a = fmaxf(arow[i] + sbg[i], 0.0f);
            acc = fmaf(sW3[i], a, acc);
        }
        const float* brow = g_b + (size_t)v * 19;
#pragma unroll
        for (int j = 0; j < 19; j++) acc = fmaf(sW3[15 + j], brow[j], acc);
    }
#pragma unroll
    for (int off = 16; off > 0; off >>= 1)
        acc += __shfl_down_sync(0xFFFFFFFFu, acc, off);
    int lane = threadIdx.x & 31, wid = threadIdx.x >> 5;
    if (lane == 0) warpsum[wid] = acc;
    __syncthreads();
    if (wid == 0) {
        int nwarps = (blockDim.x + 31) >> 5;
        float s = (lane < nwarps) ? warpsum[lane] : 0.0f;
#pragma unroll
        for (int off = 16; off > 0; off >>= 1)
            s += __shfl_down_sync(0xFFFFFFFFu, s, off);
        if (lane == 0) atomicAdd(&g_sum, s);
    }
}

__global__ void k_out(const float* __restrict__ b3, float* __restrict__ out) {
    out[0] = tanhf(g_sum / (float)NN + b3[0]);
}

extern "C" void kernel_launch(void* const* d_in, const int* in_sizes, int n_in,
                              void* d_out, int out_size) {
    const float* x1    = (const float*)d_in[0];
    const float* x2    = (const float*)d_in[1];
    const void*  edges = d_in[2];
    const float* W1    = (const float*)d_in[3];
    const float* b1    = (const float*)d_in[4];
    const float* Wg    = (const float*)d_in[5];
    const float* bg    = (const float*)d_in[6];
    const float* W3    = (const float*)d_in[7];
    const float* b3    = (const float*)d_in[8];
    const float* W4    = (const float*)d_in[9];
    const float* b4    = (const float*)d_in[10];
    float* out = (float*)d_out;

    const int TB = 256;
    const int gN  = (NN + TB - 1) / TB;
    const int gE2 = (NE / 2 + TB - 1) / TB;
    const int gG  = (NN + 63) / 64;   // 4 threads/node, 64 nodes/block

    k_init<<<gN, TB>>>((const int*)edges);
    k_deg<<<gE2, TB>>>(edges);
    k_scan1<<<SCAN_NBLK, SCAN_CHUNK>>>();
    k_scan2<<<1, 128>>>();
    k_scan3<<<gN, TB>>>();
    k_dscan<<<1, DBINS>>>();
    k_dplace<<<gN, TB>>>();
    k_place<<<gE2, TB>>>(edges);
    k_ab<<<gN, TB>>>(x1, x2, W4, b4, W1, b1, bg);
    for (int it = 0; it < 5; it++) {
        k_H<<<gN, TB>>>(Wg, bg);
        k_gather<<<gG, TB>>>();
    }
    k_final<<<gN, TB>>>(W3, bg);
    k_out<<<1, 1>>>(b3, out);
}

// round 14
// speedup vs baseline: 1.3137x; 1.3137x over previous
#include <cuda_runtime.h>
#include <math.h>

#define NN 100000
#define NB 5000
#define NE 3200000
#define SCAN_CHUNK 1024
#define SCAN_NBLK ((NN + SCAN_CHUNK - 1) / SCAN_CHUNK)   // 98

// ---- device scratch ----
__device__ __align__(16) float g_h[NN * 16];    // pre-scaled h' rows = dinv[v]*h[v] (slot 15 = 0)
__device__ __align__(16) float g_agg[NN * 16];  // padded agg
__device__ float g_b[NN * 19];
__device__ int   g_rows_s[NE];   // CSC: source row per edge, sorted by col (index only!)
__device__ int   g_cnt[NN];
__device__ int   g_off[NN];
__device__ int   g_cursor[NN];
__device__ int   g_bsum[SCAN_NBLK];
__device__ float g_dinv[NN];
__device__ float g_sum;
__device__ int   g_is64;

// ---- detect edge dtype + init counters ----
__global__ void k_init(const int* __restrict__ ewords) {
    int v = blockIdx.x * blockDim.x + threadIdx.x;
    if (v < NN) { g_cnt[v] = 0; g_cursor[v] = 0; }
    if (v == 0) {
        int nonzero = 0;
        for (int i = 0; i < 64; i++) nonzero |= ewords[2 * i + 1];
        g_is64 = (nonzero == 0) ? 1 : 0;
        g_sum = 0.0f;
    }
}

// ---- in-degree histogram over col (2 edges/thread, vector loads) ----
__global__ void k_deg(const void* __restrict__ edges) {
    int i = blockIdx.x * blockDim.x + threadIdx.x;
    if (i >= NE / 2) return;
    int c0, c1;
    if (g_is64) {
        longlong2 cc = ((const longlong2*)edges)[NE / 2 + i];
        c0 = (int)cc.x; c1 = (int)cc.y;
    } else {
        int2 cc = ((const int2*)edges)[NE / 2 + i];
        c0 = cc.x; c1 = cc.y;
    }
    if ((unsigned)c0 < (unsigned)NN) atomicAdd(&g_cnt[c0], 1);
    if ((unsigned)c1 < (unsigned)NN) atomicAdd(&g_cnt[c1], 1);
}

// ---- blocked exclusive scan of cnt -> off ----
__global__ void k_scan1() {
    __shared__ int s[SCAN_CHUNK];
    int i = blockIdx.x * SCAN_CHUNK + threadIdx.x;
    int v = (i < NN) ? g_cnt[i] : 0;
    s[threadIdx.x] = v;
    __syncthreads();
    for (int d = 1; d < SCAN_CHUNK; d <<= 1) {
        int t = (threadIdx.x >= d) ? s[threadIdx.x - d] : 0;
        __syncthreads();
        s[threadIdx.x] += t;
        __syncthreads();
    }
    if (i < NN) g_off[i] = s[threadIdx.x] - v;
    if (threadIdx.x == SCAN_CHUNK - 1) g_bsum[blockIdx.x] = s[SCAN_CHUNK - 1];
}

__global__ void k_scan2() {
    __shared__ int s[128];
    int tid = threadIdx.x;
    int v = (tid < SCAN_NBLK) ? g_bsum[tid] : 0;
    s[tid] = v;
    __syncthreads();
    for (int d = 1; d < 128; d <<= 1) {
        int t = (tid >= d) ? s[tid - d] : 0;
        __syncthreads();
        s[tid] += t;
        __syncthreads();
    }
    if (tid < SCAN_NBLK) g_bsum[tid] = s[tid] - v;
}

// ---- scan fixup + dinv ----
__global__ void k_scan3() {
    int i = blockIdx.x * blockDim.x + threadIdx.x;
    if (i >= NN) return;
    g_off[i] += g_bsum[i / SCAN_CHUNK];
    float d = (float)(g_cnt[i] + 1);
    g_dinv[i] = 1.0f / sqrtf(d);
}

// ---- place edges into CSC: index-only 4B store per edge ----
__global__ void k_place(const void* __restrict__ edges) {
    int i = blockIdx.x * blockDim.x + threadIdx.x;
    if (i >= NE / 2) return;
    int r0, r1, c0, c1;
    if (g_is64) {
        longlong2 rr = ((const longlong2*)edges)[i];
        longlong2 cc = ((const longlong2*)edges)[NE / 2 + i];
        r0 = (int)rr.x; r1 = (int)rr.y;
        c0 = (int)cc.x; c1 = (int)cc.y;
    } else {
        int2 rr = ((const int2*)edges)[i];
        int2 cc = ((const int2*)edges)[NE / 2 + i];
        r0 = rr.x; r1 = rr.y;
        c0 = cc.x; c1 = cc.y;
    }
    if ((unsigned)r0 >= (unsigned)NN) r0 = 0;
    if ((unsigned)r1 >= (unsigned)NN) r1 = 0;
    if ((unsigned)c0 >= (unsigned)NN) c0 = 0;
    if ((unsigned)c1 >= (unsigned)NN) c1 = 0;
    int p0 = atomicAdd(&g_cursor[c0], 1);
    g_rows_s[g_off[c0] + p0] = r0;
    int p1 = atomicAdd(&g_cursor[c1], 1);
    g_rows_s[g_off[c1] + p1] = r1;
}

// ---- b = [x1|x2t] W4^T + b4 ; agg0 = x1 W1^T + b1 - bg ----
__global__ void k_ab(const float* __restrict__ x1, const float* __restrict__ x2,
                     const float* __restrict__ W4, const float* __restrict__ b4,
                     const float* __restrict__ W1, const float* __restrict__ b1,
                     const float* __restrict__ bg) {
    __shared__ float sW4[19 * 19], sb4[19], sW1[15 * 15], sb1[15], sbg[15];
    for (int i = threadIdx.x; i < 19 * 19; i += blockDim.x) sW4[i] = W4[i];
    for (int i = threadIdx.x; i < 15 * 15; i += blockDim.x) sW1[i] = W1[i];
    if (threadIdx.x < 19) sb4[threadIdx.x] = b4[threadIdx.x];
    if (threadIdx.x < 15) { sb1[threadIdx.x] = b1[threadIdx.x]; sbg[threadIdx.x] = bg[threadIdx.x]; }
    __syncthreads();

    int v = blockIdx.x * blockDim.x + threadIdx.x;
    if (v >= NN) return;

    float in[19];
    const float* x1r = x1 + (size_t)v * 15;
#pragma unroll
    for (int k = 0; k < 15; k++) in[k] = x1r[k];
    const float* x2r = x2 + (size_t)(v % NB) * 4;
#pragma unroll
    for (int k = 0; k < 4; k++) in[15 + k] = x2r[k];

    float* brow = g_b + (size_t)v * 19;
#pragma unroll
    for (int j = 0; j < 19; j++) {
        float acc = sb4[j];
#pragma unroll
        for (int k = 0; k < 19; k++) acc = fmaf(sW4[j * 19 + k], in[k], acc);
        brow[j] = acc;
    }

    float* arow = g_agg + (size_t)v * 16;
#pragma unroll
    for (int i = 0; i < 15; i++) {
        float acc = sb1[i] - sbg[i];
#pragma unroll
        for (int k = 0; k < 15; k++) acc = fmaf(sW1[i * 15 + k], in[k], acc);
        arow[i] = acc;
    }
    arow[15] = 0.0f;
}

// ---- kernel H: a = relu(agg+bg); h' = dinv[v] * (Wg [a;b]) ----
__global__ void k_H(const float* __restrict__ Wg, const float* __restrict__ bg) {
    __shared__ float sWg[15 * 34], sbg[15];
    for (int i = threadIdx.x; i < 15 * 34; i += blockDim.x) sWg[i] = Wg[i];
    if (threadIdx.x < 15) sbg[threadIdx.x] = bg[threadIdx.x];
    __syncthreads();

    int v = blockIdx.x * blockDim.x + threadIdx.x;
    if (v >= NN) return;

    float a[15], bb[19];
    const float* arow = g_agg + (size_t)v * 16;
#pragma unroll
    for (int i = 0; i < 15; i++) a[i] = fmaxf(arow[i] + sbg[i], 0.0f);
    const float* brow = g_b + (size_t)v * 19;
#pragma unroll
    for (int j = 0; j < 19; j++) bb[j] = brow[j];

    float dv = g_dinv[v];
    float* hrow = g_h + (size_t)v * 16;
#pragma unroll
    for (int o = 0; o < 15; o++) {
        float acc = 0.0f;
        const float* w = sWg + o * 34;
#pragma unroll
        for (int k = 0; k < 15; k++) acc = fmaf(w[k], a[k], acc);
#pragma unroll
        for (int k = 0; k < 19; k++) acc = fmaf(w[15 + k], bb[k], acc);
        hrow[o] = acc * dv;          // pre-scaled h'
    }
    hrow[15] = 0.0f;
}

__device__ __forceinline__ float4 add4(float4 a, float4 p) {
    a.x += p.x; a.y += p.y; a.z += p.z; a.w += p.w;
    return a;
}

// ---- gather: agg[v] = dinv[v] * ( h'[v] + sum_j h'[rows_s[j]] ) ----
// 4 threads/node, float4 rows, weight-free inner loop
__global__ void k_gather() {
    int v = blockIdx.x * 64 + (threadIdx.x >> 2);   // 256 threads = 64 nodes/block
    int t = threadIdx.x & 3;                        // float4 quarter of the row
    if (v >= NN) return;

    int off = g_off[v];
    int cnt = g_cnt[v];
    const int* __restrict__ ap = g_rows_s + off;
    const float4* __restrict__ h4 = reinterpret_cast<const float4*>(g_h);

    float4 acc = h4[(size_t)v * 4 + t];             // self term h'[v]
    float4 ac1 = make_float4(0.f, 0.f, 0.f, 0.f);

    int j = 0;
    for (; j + 4 <= cnt; j += 4) {
        int r0 = __ldg(ap + j + 0);
        int r1 = __ldg(ap + j + 1);
        int r2 = __ldg(ap + j + 2);
        int r3 = __ldg(ap + j + 3);
        float4 p0 = h4[(size_t)r0 * 4 + t];
        float4 p1 = h4[(size_t)r1 * 4 + t];
        float4 p2 = h4[(size_t)r2 * 4 + t];
        float4 p3 = h4[(size_t)r3 * 4 + t];
        acc = add4(acc, p0);
        ac1 = add4(ac1, p1);
        acc = add4(acc, p2);
        ac1 = add4(ac1, p3);
    }
    for (; j < cnt; j++) {
        int r = __ldg(ap + j);
        acc = add4(acc, h4[(size_t)r * 4 + t]);
    }
    float dv = g_dinv[v];
    acc.x = (acc.x + ac1.x) * dv;
    acc.y = (acc.y + ac1.y) * dv;
    acc.z = (acc.z + ac1.z) * dv;
    acc.w = (acc.w + ac1.w) * dv;
    reinterpret_cast<float4*>(g_agg)[(size_t)v * 4 + t] = acc;   // coalesced STG.128
}

// ---- final: a = relu(agg+bg); sum_v W3 . [a;b] ----
__global__ void k_final(const float* __restrict__ W3, const float* __restrict__ bg) {
    __shared__ float sW3[34], sbg[15];
    __shared__ float warpsum[32];
    if (threadIdx.x < 34) sW3[threadIdx.x] = W3[threadIdx.x];
    if (threadIdx.x < 15) sbg[threadIdx.x] = bg[threadIdx.x];
    __syncthreads();

    int v = blockIdx.x * blockDim.x + threadIdx.x;
    float acc = 0.0f;
    if (v < NN) {
        const float* arow = g_agg + (size_t)v * 16;
#pragma unroll
        for (int i = 0; i < 15; i++) {
            float a = fmaxf(arow[i] + sbg[i], 0.0f);
            acc = fmaf(sW3[i], a, acc);
        }
        const float* brow = g_b + (size_t)v * 19;
#pragma unroll
        for (int j = 0; j < 19; j++) acc = fmaf(sW3[15 + j], brow[j], acc);
    }
#pragma unroll
    for (int off = 16; off > 0; off >>= 1)
        acc += __shfl_down_sync(0xFFFFFFFFu, acc, off);
    int lane = threadIdx.x & 31, wid = threadIdx.x >> 5;
    if (lane == 0) warpsum[wid] = acc;
    __syncthreads();
    if (wid == 0) {
        int nwarps = (blockDim.x + 31) >> 5;
        float s = (lane < nwarps) ? warpsum[lane] : 0.0f;
#pragma unroll
        for (int off = 16; off > 0; off >>= 1)
            s += __shfl_down_sync(0xFFFFFFFFu, s, off);
        if (lane == 0) atomicAdd(&g_sum, s);
    }
}

__global__ void k_out(const float* __restrict__ b3, float* __restrict__ out) {
    out[0] = tanhf(g_sum / (float)NN + b3[0]);
}

extern "C" void kernel_launch(void* const* d_in, const int* in_sizes, int n_in,
                              void* d_out, int out_size) {
    const float* x1    = (const float*)d_in[0];
    const float* x2    = (const float*)d_in[1];
    const void*  edges = d_in[2];
    const float* W1    = (const float*)d_in[3];
    const float* b1    = (const float*)d_in[4];
    const float* Wg    = (const float*)d_in[5];
    const float* bg    = (const float*)d_in[6];
    const float* W3    = (const float*)d_in[7];
    const float* b3    = (const float*)d_in[8];
    const float* W4    = (const float*)d_in[9];
    const float* b4    = (const float*)d_in[10];
    float* out = (float*)d_out;

    const int TB = 256;
    const int gN  = (NN + TB - 1) / TB;
    const int gE2 = (NE / 2 + TB - 1) / TB;
    const int gG  = (NN + 63) / 64;   // 4 threads/node, 64 nodes/block

    k_init<<<gN, TB>>>((const int*)edges);
    k_deg<<<gE2, TB>>>(edges);
    k_scan1<<<SCAN_NBLK, SCAN_CHUNK>>>();
    k_scan2<<<1, 128>>>();
    k_scan3<<<gN, TB>>>();
    k_place<<<gE2, TB>>>(edges);
    k_ab<<<gN, TB>>>(x1, x2, W4, b4, W1, b1, bg);
    for (int it = 0; it < 5; it++) {
        k_H<<<gN, TB>>>(Wg, bg);
        k_gather<<<gG, TB>>>();
    }
    k_final<<<gN, TB>>>(W3, bg);
    k_out<<<1, 1>>>(b3, out);
}

// round 16
// speedup vs baseline: 1.3504x; 1.0279x over previous
#include <cuda_runtime.h>
#include <math.h>

#define NN 100000
#define NB 5000
#define NE 3200000
#define SCAN_CHUNK 1024
#define SCAN_NBLK ((NN + SCAN_CHUNK - 1) / SCAN_CHUNK)   // 98

// ---- device scratch ----
__device__ __align__(16) float g_h[2][NN * 16]; // double-buffered pre-scaled h' rows
__device__ __align__(16) float g_agg[NN * 16];  // final-iteration agg
__device__ __align__(16) float g_b[NN * 20];    // b rows padded to 20 (slot 19 = garbage ok)
__device__ int   g_rows_s[NE];   // CSC: source row per edge (index only)
__device__ int   g_cnt[NN];
__device__ int   g_off[NN];
__device__ int   g_cursor[NN];
__device__ int   g_bsum[SCAN_NBLK];
__device__ float g_dinv[NN];
__device__ float g_sum;
__device__ int   g_is64;

// ---- detect edge dtype + init counters ----
__global__ void k_init(const int* __restrict__ ewords) {
    int v = blockIdx.x * blockDim.x + threadIdx.x;
    if (v < NN) { g_cnt[v] = 0; g_cursor[v] = 0; }
    if (v == 0) {
        int nonzero = 0;
        for (int i = 0; i < 64; i++) nonzero |= ewords[2 * i + 1];
        g_is64 = (nonzero == 0) ? 1 : 0;
        g_sum = 0.0f;
    }
}

// ---- in-degree histogram over col (2 edges/thread) ----
__global__ void k_deg(const void* __restrict__ edges) {
    int i = blockIdx.x * blockDim.x + threadIdx.x;
    if (i >= NE / 2) return;
    int c0, c1;
    if (g_is64) {
        longlong2 cc = ((const longlong2*)edges)[NE / 2 + i];
        c0 = (int)cc.x; c1 = (int)cc.y;
    } else {
        int2 cc = ((const int2*)edges)[NE / 2 + i];
        c0 = cc.x; c1 = cc.y;
    }
    if ((unsigned)c0 < (unsigned)NN) atomicAdd(&g_cnt[c0], 1);
    if ((unsigned)c1 < (unsigned)NN) atomicAdd(&g_cnt[c1], 1);
}

// ---- blocked exclusive scan of cnt -> off ----
__global__ void k_scan1() {
    __shared__ int s[SCAN_CHUNK];
    int i = blockIdx.x * SCAN_CHUNK + threadIdx.x;
    int v = (i < NN) ? g_cnt[i] : 0;
    s[threadIdx.x] = v;
    __syncthreads();
    for (int d = 1; d < SCAN_CHUNK; d <<= 1) {
        int t = (threadIdx.x >= d) ? s[threadIdx.x - d] : 0;
        __syncthreads();
        s[threadIdx.x] += t;
        __syncthreads();
    }
    if (i < NN) g_off[i] = s[threadIdx.x] - v;
    if (threadIdx.x == SCAN_CHUNK - 1) g_bsum[blockIdx.x] = s[SCAN_CHUNK - 1];
}

__global__ void k_scan2() {
    __shared__ int s[128];
    int tid = threadIdx.x;
    int v = (tid < SCAN_NBLK) ? g_bsum[tid] : 0;
    s[tid] = v;
    __syncthreads();
    for (int d = 1; d < 128; d <<= 1) {
        int t = (tid >= d) ? s[tid - d] : 0;
        __syncthreads();
        s[tid] += t;
        __syncthreads();
    }
    if (tid < SCAN_NBLK) g_bsum[tid] = s[tid] - v;
}

// ---- scan fixup + dinv ----
__global__ void k_scan3() {
    int i = blockIdx.x * blockDim.x + threadIdx.x;
    if (i >= NN) return;
    g_off[i] += g_bsum[i / SCAN_CHUNK];
    float d = (float)(g_cnt[i] + 1);
    g_dinv[i] = 1.0f / sqrtf(d);
}

// ---- place edges into CSC: index-only 4B store per edge ----
__global__ void k_place(const void* __restrict__ edges) {
    int i = blockIdx.x * blockDim.x + threadIdx.x;
    if (i >= NE / 2) return;
    int r0, r1, c0, c1;
    if (g_is64) {
        longlong2 rr = ((const longlong2*)edges)[i];
        longlong2 cc = ((const longlong2*)edges)[NE / 2 + i];
        r0 = (int)rr.x; r1 = (int)rr.y;
        c0 = (int)cc.x; c1 = (int)cc.y;
    } else {
        int2 rr = ((const int2*)edges)[i];
        int2 cc = ((const int2*)edges)[NE / 2 + i];
        r0 = rr.x; r1 = rr.y;
        c0 = cc.x; c1 = cc.y;
    }
    if ((unsigned)r0 >= (unsigned)NN) r0 = 0;
    if ((unsigned)r1 >= (unsigned)NN) r1 = 0;
    if ((unsigned)c0 >= (unsigned)NN) c0 = 0;
    if ((unsigned)c1 >= (unsigned)NN) c1 = 0;
    int p0 = atomicAdd(&g_cursor[c0], 1);
    g_rows_s[g_off[c0] + p0] = r0;
    int p1 = atomicAdd(&g_cursor[c1], 1);
    g_rows_s[g_off[c1] + p1] = r1;
}

// ---- fused: b = [x1|x2t]W4^T+b4 ; a0 = relu(x1 W1^T + b1) ; h'0 = dinv*(Wg [a0;b]) ----
__global__ void k_abh(const float* __restrict__ x1, const float* __restrict__ x2,
                      const float* __restrict__ W4, const float* __restrict__ b4,
                      const float* __restrict__ W1, const float* __restrict__ b1,
                      const float* __restrict__ Wg) {
    __shared__ float sW4[19 * 19], sb4[19], sW1[15 * 15], sb1[15], sWg[15 * 34];
    for (int i = threadIdx.x; i < 19 * 19; i += blockDim.x) sW4[i] = W4[i];
    for (int i = threadIdx.x; i < 15 * 15; i += blockDim.x) sW1[i] = W1[i];
    for (int i = threadIdx.x; i < 15 * 34; i += blockDim.x) sWg[i] = Wg[i];
    if (threadIdx.x < 19) sb4[threadIdx.x] = b4[threadIdx.x];
    if (threadIdx.x < 15) sb1[threadIdx.x] = b1[threadIdx.x];
    __syncthreads();

    int v = blockIdx.x * blockDim.x + threadIdx.x;
    if (v >= NN) return;

    float in[19];
    const float* x1r = x1 + (size_t)v * 15;
#pragma unroll
    for (int k = 0; k < 15; k++) in[k] = x1r[k];
    const float* x2r = x2 + (size_t)(v % NB) * 4;
#pragma unroll
    for (int k = 0; k < 4; k++) in[15 + k] = x2r[k];

    float bb[19];
    float* brow = g_b + (size_t)v * 20;
#pragma unroll
    for (int j = 0; j < 19; j++) {
        float acc = sb4[j];
#pragma unroll
        for (int k = 0; k < 19; k++) acc = fmaf(sW4[j * 19 + k], in[k], acc);
        bb[j] = acc;
        brow[j] = acc;
    }

    float a0[15];
#pragma unroll
    for (int i = 0; i < 15; i++) {
        float acc = sb1[i];
#pragma unroll
        for (int k = 0; k < 15; k++) acc = fmaf(sW1[i * 15 + k], in[k], acc);
        a0[i] = fmaxf(acc, 0.0f);
    }

    float dv = g_dinv[v];
    float* hrow = g_h[0] + (size_t)v * 16;
#pragma unroll
    for (int o = 0; o < 15; o++) {
        float acc = 0.0f;
        const float* w = sWg + o * 34;
#pragma unroll
        for (int k = 0; k < 15; k++) acc = fmaf(w[k], a0[k], acc);
#pragma unroll
        for (int k = 0; k < 19; k++) acc = fmaf(w[15 + k], bb[k], acc);
        hrow[o] = acc * dv;
    }
    hrow[15] = 0.0f;
}

__device__ __forceinline__ float4 add4(float4 a, float4 p) {
    a.x += p.x; a.y += p.y; a.z += p.z; a.w += p.w;
    return a;
}

// ---- fused gather + next-h' epilogue ----
// 4 threads/node. Reads h'[buf], computes agg in regs.
// last==0: writes h'[buf^1] = dinv*(Wg [relu(agg+bg); b]).  last==1: writes g_agg.
__global__ void k_gfused(const float* __restrict__ Wg, const float* __restrict__ bg,
                         int buf, int last) {
    __shared__ float sWg[15 * 34], sbg[16];
    for (int i = threadIdx.x; i < 15 * 34; i += blockDim.x) sWg[i] = Wg[i];
    if (threadIdx.x < 15) sbg[threadIdx.x] = bg[threadIdx.x];
    if (threadIdx.x == 15) sbg[15] = 0.0f;
    __syncthreads();

    int v = blockIdx.x * 64 + (threadIdx.x >> 2);   // 256 threads = 64 nodes/block
    int t = threadIdx.x & 3;
    if (v >= NN) return;

    int off = g_off[v];
    int cnt = g_cnt[v];
    const int* __restrict__ ap = g_rows_s + off;
    const float4* __restrict__ h4 = reinterpret_cast<const float4*>(g_h[buf]);

    float4 acc = h4[(size_t)v * 4 + t];             // self term h'[v]
    float4 ac1 = make_float4(0.f, 0.f, 0.f, 0.f);

    int j = 0;
    for (; j + 4 <= cnt; j += 4) {
        int r0 = __ldg(ap + j + 0);
        int r1 = __ldg(ap + j + 1);
        int r2 = __ldg(ap + j + 2);
        int r3 = __ldg(ap + j + 3);
        float4 p0 = h4[(size_t)r0 * 4 + t];
        float4 p1 = h4[(size_t)r1 * 4 + t];
        float4 p2 = h4[(size_t)r2 * 4 + t];
        float4 p3 = h4[(size_t)r3 * 4 + t];
        acc = add4(acc, p0);
        ac1 = add4(ac1, p1);
        acc = add4(acc, p2);
        ac1 = add4(ac1, p3);
    }
    for (; j < cnt; j++) {
        int r = __ldg(ap + j);
        acc = add4(acc, h4[(size_t)r * 4 + t]);
    }
    float dv = g_dinv[v];
    acc.x = (acc.x + ac1.x) * dv;
    acc.y = (acc.y + ac1.y) * dv;
    acc.z = (acc.z + ac1.z) * dv;
    acc.w = (acc.w + ac1.w) * dv;

    if (last) {
        reinterpret_cast<float4*>(g_agg)[(size_t)v * 4 + t] = acc;
        return;
    }

    // epilogue: a quarter for this lane (relu(agg+bg); slot 15 -> 0)
    float aq[4];
    aq[0] = fmaxf(acc.x + sbg[4 * t + 0], 0.0f);
    aq[1] = fmaxf(acc.y + sbg[4 * t + 1], 0.0f);
    aq[2] = fmaxf(acc.z + sbg[4 * t + 2], 0.0f);
    aq[3] = (t < 3) ? fmaxf(acc.w + sbg[4 * t + 3], 0.0f) : 0.0f;

    // distribute all 16 a-values across the 4-lane group
    float a_all[16];
#pragma unroll
    for (int src = 0; src < 4; src++) {
#pragma unroll
        for (int c = 0; c < 4; c++)
            a_all[src * 4 + c] = __shfl_sync(0xFFFFFFFFu, aq[c], src, 4);
    }

    // full padded-b row (stride 20, 5 x float4)
    float bb[20];
    const float4* brow4 = reinterpret_cast<const float4*>(g_b + (size_t)v * 20);
#pragma unroll
    for (int q = 0; q < 5; q++) {
        float4 x = brow4[q];
        bb[q * 4 + 0] = x.x; bb[q * 4 + 1] = x.y;
        bb[q * 4 + 2] = x.z; bb[q * 4 + 3] = x.w;
    }

    // this lane's 4 outputs of h'_next = dinv * (Wg [a;b])
    float4 hn;
    float* hp = reinterpret_cast<float*>(&hn);
#pragma unroll
    for (int c = 0; c < 4; c++) {
        int o = 4 * t + c;
        float acc2 = 0.0f;
        if (o < 15) {
            const float* w = sWg + o * 34;
#pragma unroll
            for (int k = 0; k < 15; k++) acc2 = fmaf(w[k], a_all[k], acc2);
#pragma unroll
            for (int k = 0; k < 19; k++) acc2 = fmaf(w[15 + k], bb[k], acc2);
            acc2 *= dv;
        }
        hp[c] = acc2;
    }
    reinterpret_cast<float4*>(g_h[buf ^ 1])[(size_t)v * 4 + t] = hn;
}

// ---- final: a = relu(agg+bg); sum_v W3 . [a;b] ----
__global__ void k_final(const float* __restrict__ W3, const float* __restrict__ bg) {
    __shared__ float sW3[34], sbg[15];
    __shared__ float warpsum[32];
    if (threadIdx.x < 34) sW3[threadIdx.x] = W3[threadIdx.x];
    if (threadIdx.x < 15) sbg[threadIdx.x] = bg[threadIdx.x];
    __syncthreads();

    int v = blockIdx.x * blockDim.x + threadIdx.x;
    float acc = 0.0f;
    if (v < NN) {
        const float* arow = g_agg + (size_t)v * 16;
#pragma unroll
        for (int i = 0; i < 15; i++) {
            float a = fmaxf(arow[i] + sbg[i], 0.0f);
            acc = fmaf(sW3[i], a, acc);
        }
        const float* brow = g_b + (size_t)v * 20;
#pragma unroll
        for (int j = 0; j < 19; j++) acc = fmaf(sW3[15 + j], brow[j], acc);
    }
#pragma unroll
    for (int off = 16; off > 0; off >>= 1)
        acc += __shfl_down_sync(0xFFFFFFFFu, acc, off);
    int lane = threadIdx.x & 31, wid = threadIdx.x >> 5;
    if (lane == 0) warpsum[wid] = acc;
    __syncthreads();
    if (wid == 0) {
        int nwarps = (blockDim.x + 31) >> 5;
        float s = (lane < nwarps) ? warpsum[lane] : 0.0f;
#pragma unroll
        for (int off = 16; off > 0; off >>= 1)
            s += __shfl_down_sync(0xFFFFFFFFu, s, off);
        if (lane == 0) atomicAdd(&g_sum, s);
    }
}

__global__ void k_out(const float* __restrict__ b3, float* __restrict__ out) {
    out[0] = tanhf(g_sum / (float)NN + b3[0]);
}

extern "C" void kernel_launch(void* const* d_in, const int* in_sizes, int n_in,
                              void* d_out, int out_size) {
    const float* x1    = (const float*)d_in[0];
    const float* x2    = (const float*)d_in[1];
    const void*  edges = d_in[2];
    const float* W1    = (const float*)d_in[3];
    const float* b1    = (const float*)d_in[4];
    const float* Wg    = (const float*)d_in[5];
    const float* bg    = (const float*)d_in[6];
    const float* W3    = (const float*)d_in[7];
    const float* b3    = (const float*)d_in[8];
    const float* W4    = (const float*)d_in[9];
    const float* b4    = (const float*)d_in[10];
    float* out = (float*)d_out;

    const int TB = 256;
    const int gN  = (NN + TB - 1) / TB;
    const int gE2 = (NE / 2 + TB - 1) / TB;
    const int gG  = (NN + 63) / 64;   // 4 threads/node, 64 nodes/block

    k_init<<<gN, TB>>>((const int*)edges);
    k_deg<<<gE2, TB>>>(edges);
    k_scan1<<<SCAN_NBLK, SCAN_CHUNK>>>();
    k_scan2<<<1, 128>>>();
    k_scan3<<<gN, TB>>>();
    k_place<<<gE2, TB>>>(edges);
    k_abh<<<gN, TB>>>(x1, x2, W4, b4, W1, b1, Wg);
    for (int it = 0; it < 5; it++) {
        k_gfused<<<gG, TB>>>(Wg, bg, it & 1, it == 4 ? 1 : 0);
    }
    k_final<<<gN, TB>>>(W3, bg);
    k_out<<<1, 1>>>(b3, out);
}